// round 11
// baseline (speedup 1.0000x reference)
#include <cuda_runtime.h>
#include <math.h>

#define BZ   4
#define CH   64
#define HH   64
#define WW   64
#define LSEQ (HH*WW)      // 4096
#define NT   (BZ*LSEQ)    // 16384
#define DI   128
#define DS   16
#define DTR  4
#define GCH  64           // chunks per batch
#define TCH  (LSEQ/GCH)   // 64 steps per chunk

// ---------------- scratch (device globals; no allocation) ----------------
__device__ float g_seq[NT*CH];
__device__ float g_xm [NT*DI];
__device__ float g_z  [NT*DI];     // holds silu(z)
__device__ float g_Cm [NT*DS];
__device__ float g_pg [NT*DI];     // yl + xc*Dp
__device__ float g_cd [NT*DI];
__device__ float g_E  [BZ*GCH*DI*DS];
__device__ float g_P  [BZ*GCH*DI*DS];
__device__ float g_H  [BZ*GCH*DI*DS];
__device__ float g_A  [DI*DS];
__device__ float g_WoT[DI*CH];     // out_proj weight transposed [d][c]
__device__ int   g_chain[DI];

__device__ __forceinline__ float siluf(float v) { return v / (1.f + __expf(-v)); }

// ======== K1: axial DW + 1x1 conv + BN + ReLU + LN + in_proj GEMM ========
// (block 0 initializes g_A/g_chain; block 1 transposes Wout -> g_WoT)
// dyn smem: t[64][68] | r[64][68] | wB (8576 floats)
__global__ __launch_bounds__(256) void k_fuse1(
        const float* __restrict__ x,
        const float* __restrict__ dwhw, const float* __restrict__ dwhb,
        const float* __restrict__ dwww, const float* __restrict__ dwwb,
        const float* __restrict__ convw, const float* __restrict__ convb,
        const float* __restrict__ bng, const float* __restrict__ bnb,
        const float* __restrict__ bnm, const float* __restrict__ bnv,
        const float* __restrict__ lng, const float* __restrict__ lnb,
        const float* __restrict__ Win, const float* __restrict__ A_log,
        const float* __restrict__ Wout) {
    extern __shared__ __align__(16) float sm1[];
    float* t  = sm1;               // [64][68]
    float* r  = sm1 + 64*68;       // [64][68]
    float* wB = sm1 + 2*64*68;     // 8576 floats
    __shared__ float mu[WW], rs[WW];
    __shared__ float sc[CH], sh[CH];
    int blk = blockIdx.x;
    int b = blk >> 6, h = blk & 63;
    int tid = threadIdx.x;

    if (blk == 0 && tid < DI) {
        int d = tid;
        float a0 = -expf(A_log[d*DS + 0]);
        int ok = 1;
        for (int s = 0; s < DS; ++s) {
            float a = -expf(A_log[d*DS + s]);
            g_A[d*DS + s] = a;
            if (fabsf(a - (float)(s+1)*a0) > 1e-3f*fabsf(a) + 1e-6f) ok = 0;
        }
        g_chain[d] = ok;
    }
    if (blk == 1) {
        for (int idx = tid; idx < DI*CH; idx += 256) {
            int c = idx & 63, d = idx >> 6;
            g_WoT[d*CH + c] = Wout[c*DI + d];
        }
    }

    if (tid < CH) {
        float s = bng[tid] * rsqrtf(bnv[tid] + 1e-5f);
        sc[tid] = s;
        sh[tid] = (convb[tid] - bnm[tid]) * s + bnb[tid];
    }
    const float* xb = x + (size_t)b*CH*LSEQ;
    for (int idx = tid; idx < CH*WW; idx += 256) {
        int c = idx >> 6, w = idx & 63;
        const float* xr = xb + c*LSEQ + h*WW;
        float xv = xr[w];
        float up = (h > 0)    ? xr[w - WW] : 0.f;
        float dn = (h < HH-1) ? xr[w + WW] : 0.f;
        float lf = (w > 0)    ? xr[w - 1]  : 0.f;
        float rt = (w < WW-1) ? xr[w + 1]  : 0.f;
        float v = xv
            + dwhw[c*3+0]*up + dwhw[c*3+1]*xv + dwhw[c*3+2]*dn + dwhb[c]
            + dwww[c*3+0]*lf + dwww[c*3+1]*xv + dwww[c*3+2]*rt + dwwb[c];
        t[c*68 + w] = v;
    }
    __syncthreads();

    // 1x1 conv (64x64x64) -> BN -> ReLU into r
    int cg = tid >> 4, tg = tid & 15;
    int co0 = cg * 4, w0 = tg * 4;
    {
        float acc[4][4] = {};
        #pragma unroll 4
        for (int ci = 0; ci < CH; ++ci) {
            float4 av = *(const float4*)&t[ci*68 + w0];
            float wv0 = __ldg(&convw[(co0+0)*CH + ci]);
            float wv1 = __ldg(&convw[(co0+1)*CH + ci]);
            float wv2 = __ldg(&convw[(co0+2)*CH + ci]);
            float wv3 = __ldg(&convw[(co0+3)*CH + ci]);
            acc[0][0] += wv0*av.x; acc[0][1] += wv0*av.y; acc[0][2] += wv0*av.z; acc[0][3] += wv0*av.w;
            acc[1][0] += wv1*av.x; acc[1][1] += wv1*av.y; acc[1][2] += wv1*av.z; acc[1][3] += wv1*av.w;
            acc[2][0] += wv2*av.x; acc[2][1] += wv2*av.y; acc[2][2] += wv2*av.z; acc[2][3] += wv2*av.w;
            acc[3][0] += wv3*av.x; acc[3][1] += wv3*av.y; acc[3][2] += wv3*av.z; acc[3][3] += wv3*av.w;
        }
        #pragma unroll
        for (int i = 0; i < 4; ++i)
            #pragma unroll
            for (int j = 0; j < 4; ++j) {
                float v = acc[i][j]*sc[co0+i] + sh[co0+i];
                r[(co0+i)*68 + w0+j] = fmaxf(v, 0.f);
            }
    }
    __syncthreads();

    if (tid < WW) {
        float m = 0.f;
        for (int c = 0; c < CH; ++c) m += r[c*68 + tid];
        m *= (1.f/CH);
        float v = 0.f;
        for (int c = 0; c < CH; ++c) { float dd = r[c*68 + tid] - m; v += dd*dd; }
        v *= (1.f/CH);
        mu[tid] = m; rs[tid] = rsqrtf(v + 1e-5f);
    }
    __syncthreads();

    int n0 = b*LSEQ + h*WW;
    for (int idx = tid; idx < CH*WW; idx += 256) {
        int w = idx >> 6, c = idx & 63;
        float rv = r[c*68 + w];
        g_seq[(size_t)(n0+w)*CH + c] = rv;
        r[c*68 + w] = (rv - mu[w]) * rs[w] * lng[c] + lnb[c];
    }

    // in_proj GEMM: hn[64tok x 64c] x Win[256 x 64]^T, 2 chunks of 128 outs
    int oo0 = cg*4, t0 = tg*4;
    for (int chunk = 0; chunk < 2; ++chunk) {
        int o0 = chunk * 128;
        __syncthreads();
        for (int idx = tid; idx < 128*CH; idx += 256) {
            int oo = idx >> 6, c = idx & 63;
            wB[c*132 + oo] = Win[(o0+oo)*CH + c];
        }
        __syncthreads();
        float acc[8][4] = {};
        #pragma unroll 2
        for (int ci = 0; ci < CH; ++ci) {
            float4 av = *(const float4*)&r[ci*68 + t0];
            float4 u  = *(const float4*)&wB[ci*132 + oo0];
            float4 v  = *(const float4*)&wB[ci*132 + oo0 + 64];
            acc[0][0] += u.x*av.x; acc[0][1] += u.x*av.y; acc[0][2] += u.x*av.z; acc[0][3] += u.x*av.w;
            acc[1][0] += u.y*av.x; acc[1][1] += u.y*av.y; acc[1][2] += u.y*av.z; acc[1][3] += u.y*av.w;
            acc[2][0] += u.z*av.x; acc[2][1] += u.z*av.y; acc[2][2] += u.z*av.z; acc[2][3] += u.z*av.w;
            acc[3][0] += u.w*av.x; acc[3][1] += u.w*av.y; acc[3][2] += u.w*av.z; acc[3][3] += u.w*av.w;
            acc[4][0] += v.x*av.x; acc[4][1] += v.x*av.y; acc[4][2] += v.x*av.z; acc[4][3] += v.x*av.w;
            acc[5][0] += v.y*av.x; acc[5][1] += v.y*av.y; acc[5][2] += v.y*av.z; acc[5][3] += v.y*av.w;
            acc[6][0] += v.z*av.x; acc[6][1] += v.z*av.y; acc[6][2] += v.z*av.z; acc[6][3] += v.z*av.w;
            acc[7][0] += v.w*av.x; acc[7][1] += v.w*av.y; acc[7][2] += v.w*av.z; acc[7][3] += v.w*av.w;
        }
        __syncthreads();
        #pragma unroll
        for (int i = 0; i < 4; ++i)
            #pragma unroll
            for (int j = 0; j < 4; ++j) {
                wB[(oo0+i)*67 + t0+j]    = acc[i][j];
                wB[(oo0+64+i)*67 + t0+j] = acc[4+i][j];
            }
        __syncthreads();
        for (int idx = tid; idx < 128*64; idx += 256) {
            int tok = idx >> 7, oo = idx & 127;
            float vv = wB[oo*67 + tok];
            int n = n0 + tok;
            if (chunk == 0) g_xm[(size_t)n*DI + oo] = vv;
            else            g_z [(size_t)n*DI + oo] = siluf(vv);   // pre-gated
        }
    }
}

// ======== K2: conv1d+SiLU + x_proj + inline-dt local chunk scan ==========
// dyn smem: xcS[64][129] | dbc[64][40]   (43.3KB -> 4+ CTAs/SM)
#define XC_PITCH 129
__global__ __launch_bounds__(256) void k_fuse2(
        const float* __restrict__ cw, const float* __restrict__ cb,
        const float* __restrict__ xpw,
        const float* __restrict__ dtpw, const float* __restrict__ dtpb,
        const float* __restrict__ Dp) {
    extern __shared__ __align__(16) float sm[];
    float* xcS = sm;                      // 64*129 = 8256 (reused for E/P staging)
    float* dbc = sm + 8256;               // 64*40  = 2560
    int blk = blockIdx.x;                 // b*64 + g
    int g = blk & 63;
    int tid = threadIdx.x;
    int n0 = blk * TCH;

    // phase A: xc = silu(conv1d(xm)); taps read g_xm directly (coalesced per tap)
    for (int idx = tid; idx < 64*DI; idx += 256) {
        int tok = idx >> 7, d = idx & 127;
        float acc = __ldg(&cb[d]);
        #pragma unroll
        for (int k = 0; k < 4; ++k) {
            int tt = tok - 3 + k;
            if (g > 0 || tt >= 0)
                acc += __ldg(&cw[d*4 + k]) * g_xm[(size_t)(n0 + tt)*DI + d];
        }
        xcS[tok*XC_PITCH + d] = siluf(acc);
    }
    __syncthreads();

    // phase B: dbc = xc @ xpw^T   (36 outs x 64 toks x 128 K)
    int eg = tid >> 4, tg = tid & 15;
    if (eg < 9) {
        int e0 = eg*4, t0 = tg*4;
        float acc[4][4] = {};
        #pragma unroll 4
        for (int ci = 0; ci < DI; ++ci) {
            float w0_ = __ldg(&xpw[(e0+0)*DI + ci]);
            float w1_ = __ldg(&xpw[(e0+1)*DI + ci]);
            float w2_ = __ldg(&xpw[(e0+2)*DI + ci]);
            float w3_ = __ldg(&xpw[(e0+3)*DI + ci]);
            float a0_ = xcS[(t0+0)*XC_PITCH + ci];
            float a1_ = xcS[(t0+1)*XC_PITCH + ci];
            float a2_ = xcS[(t0+2)*XC_PITCH + ci];
            float a3_ = xcS[(t0+3)*XC_PITCH + ci];
            acc[0][0] += w0_*a0_; acc[0][1] += w0_*a1_; acc[0][2] += w0_*a2_; acc[0][3] += w0_*a3_;
            acc[1][0] += w1_*a0_; acc[1][1] += w1_*a1_; acc[1][2] += w1_*a2_; acc[1][3] += w1_*a3_;
            acc[2][0] += w2_*a0_; acc[2][1] += w2_*a1_; acc[2][2] += w2_*a2_; acc[2][3] += w2_*a3_;
            acc[3][0] += w3_*a0_; acc[3][1] += w3_*a1_; acc[3][2] += w3_*a2_; acc[3][3] += w3_*a3_;
        }
        #pragma unroll
        for (int i = 0; i < 4; ++i)
            #pragma unroll
            for (int j = 0; j < 4; ++j) dbc[(t0+j)*40 + e0+i] = acc[i][j];
    }
    __syncthreads();

    // export C for K4
    for (int idx = tid; idx < 64*DS; idx += 256) {
        int tok = idx >> 4, s = idx & 15;
        g_Cm[(size_t)(n0+tok)*DS + s] = dbc[tok*40 + 20 + s];
    }

    // scan: paired lanes (d = tid>>1, half = tid&1), dt computed inline
    int d = tid >> 1, half = tid & 1;
    float hreg[8];
    float cd = 0.f;
    {
        float a0 = g_A[d*DS];
        bool chain = (g_chain[d] != 0);
        float As[8];
        #pragma unroll
        for (int j = 0; j < 8; ++j) As[j] = g_A[d*DS + half*8 + j];
        #pragma unroll
        for (int j = 0; j < 8; ++j) hreg[j] = 0.f;
        float w0 = __ldg(&dtpw[d*DTR+0]), w1 = __ldg(&dtpw[d*DTR+1]);
        float w2 = __ldg(&dtpw[d*DTR+2]), w3 = __ldg(&dtpw[d*DTR+3]);
        float bia = __ldg(&dtpb[d]);
        float dpv = __ldg(&Dp[d]);
        const float* Bp = dbc + 4 + half*8;
        const float* Cp = dbc + 20 + half*8;

        if (chain) {
            for (int st = 0; st < TCH; ++st) {
                const float* row = dbc + st*40;
                float raw = bia + row[0]*w0 + row[1]*w1 + row[2]*w2 + row[3]*w3;
                float dtv = (raw > 20.f) ? raw : log1pf(__expf(raw));
                float xcv = xcS[st*XC_PITCH + d];
                float dxv = dtv * xcv;
                cd += dtv;
                float e1 = __expf(dtv * a0);
                float e2 = e1*e1, e3 = e2*e1, e4 = e2*e2;
                float e5 = e4*e1, e6 = e4*e2, e7 = e4*e3, e8 = e4*e4;
                float base = half ? e8 : 1.f;
                float p0 = base*e1, p1 = base*e2, p2 = base*e3, p3 = base*e4;
                float p4 = base*e5, p5 = base*e6, p6 = base*e7, p7 = base*e8;
                const float* Bs = Bp + st*40;
                const float* Cs_ = Cp + st*40;
                float y;
                hreg[0] = p0*hreg[0] + dxv*Bs[0];  y  = hreg[0]*Cs_[0];
                hreg[1] = p1*hreg[1] + dxv*Bs[1];  y += hreg[1]*Cs_[1];
                hreg[2] = p2*hreg[2] + dxv*Bs[2];  y += hreg[2]*Cs_[2];
                hreg[3] = p3*hreg[3] + dxv*Bs[3];  y += hreg[3]*Cs_[3];
                hreg[4] = p4*hreg[4] + dxv*Bs[4];  y += hreg[4]*Cs_[4];
                hreg[5] = p5*hreg[5] + dxv*Bs[5];  y += hreg[5]*Cs_[5];
                hreg[6] = p6*hreg[6] + dxv*Bs[6];  y += hreg[6]*Cs_[6];
                hreg[7] = p7*hreg[7] + dxv*Bs[7];  y += hreg[7]*Cs_[7];
                y += __shfl_xor_sync(0xffffffffu, y, 1);
                if (half == 0) {
                    size_t gi = (size_t)(n0+st)*DI + d;
                    g_pg[gi] = y + xcv*dpv; g_cd[gi] = cd;
                }
            }
        } else {
            for (int st = 0; st < TCH; ++st) {
                const float* row = dbc + st*40;
                float raw = bia + row[0]*w0 + row[1]*w1 + row[2]*w2 + row[3]*w3;
                float dtv = (raw > 20.f) ? raw : log1pf(__expf(raw));
                float xcv = xcS[st*XC_PITCH + d];
                float dxv = dtv * xcv;
                cd += dtv;
                const float* Bs = Bp + st*40;
                const float* Cs_ = Cp + st*40;
                float y = 0.f;
                #pragma unroll
                for (int j = 0; j < 8; ++j) {
                    float dA = __expf(dtv * As[j]);
                    hreg[j] = dA*hreg[j] + dxv*Bs[j];
                    y += hreg[j]*Cs_[j];
                }
                y += __shfl_xor_sync(0xffffffffu, y, 1);
                if (half == 0) {
                    size_t gi = (size_t)(n0+st)*DI + d;
                    g_pg[gi] = y + xcv*dpv; g_cd[gi] = cd;
                }
            }
        }
    }
    __syncthreads();   // all xcS reads done before staging overwrites it
    {
        float* stgE = xcS;          // 2048 floats
        float* stgP = xcS + 2048;   // 2048 floats
        float a0 = g_A[d*DS];
        bool chain = (g_chain[d] != 0);
        int sb = d*DS + half*8;
        #pragma unroll
        for (int j = 0; j < 8; ++j) stgE[sb + j] = hreg[j];
        if (chain) {
            float q = __expf(a0 * cd);
            float q2 = q*q, q3 = q2*q, q4 = q2*q2;
            float q5 = q4*q, q6 = q4*q2, q7 = q4*q3, q8 = q4*q4;
            float base = half ? q8 : 1.f;
            stgP[sb+0] = base*q;  stgP[sb+1] = base*q2;
            stgP[sb+2] = base*q3; stgP[sb+3] = base*q4;
            stgP[sb+4] = base*q5; stgP[sb+5] = base*q6;
            stgP[sb+6] = base*q7; stgP[sb+7] = base*q8;
        } else {
            #pragma unroll
            for (int j = 0; j < 8; ++j)
                stgP[sb + j] = __expf(g_A[d*DS + half*8 + j]*cd);
        }
    }
    __syncthreads();
    for (int idx = tid; idx < DI*DS; idx += 256) {
        g_E[(size_t)blk*DI*DS + idx] = xcS[idx];
        g_P[(size_t)blk*DI*DS + idx] = xcS[2048 + idx];
    }
}

// ---------------- K3: sequential chunk-state combine (pipelined) ---------
__global__ __launch_bounds__(128) void k_comb() {
    int i = blockIdx.x * 128 + threadIdx.x;    // 8192 = BZ*DI*DS
    int b = i >> 11, r = i & 2047;
    size_t base = (size_t)b*GCH*(DI*DS) + r;

    float Pb[8], Eb[8];
    #pragma unroll
    for (int j = 0; j < 8; ++j) {
        Pb[j] = g_P[base + (size_t)j*(DI*DS)];
        Eb[j] = g_E[base + (size_t)j*(DI*DS)];
    }
    float h = 0.f;
    #pragma unroll
    for (int grp = 0; grp < 8; ++grp) {
        float Pn[8], En[8];
        if (grp < 7) {
            #pragma unroll
            for (int j = 0; j < 8; ++j) {
                size_t o = base + (size_t)((grp+1)*8 + j)*(DI*DS);
                Pn[j] = g_P[o];
                En[j] = g_E[o];
            }
        }
        #pragma unroll
        for (int j = 0; j < 8; ++j) {
            g_H[base + (size_t)(grp*8 + j)*(DI*DS)] = h;
            h = fmaf(Pb[j], h, Eb[j]);
        }
        if (grp < 7) {
            #pragma unroll
            for (int j = 0; j < 8; ++j) { Pb[j] = Pn[j]; Eb[j] = En[j]; }
        }
    }
}

// ======== K4: correction + gating + out_proj + residual + NCHW ===========
// dyn smem (48.6KB): ysT[128][68] | Hs[128][17] | Cs[64][16] | a0s | chs
__global__ __launch_bounds__(256, 4) void k_fuse4(float* __restrict__ out) {
    extern __shared__ __align__(16) float sm[];
    float* ysT  = sm;                    // [128][68]  8704 floats
    float* Hs   = sm + 8704;             // [128][17]  2176
    float* Cs   = sm + 10880;            // [64][16]   1024
    float* a0s  = sm + 11904;            // [128]
    float* chs  = sm + 12032;            // [128]
    int blk = blockIdx.x;                // b*64 + g
    int b = blk >> 6, g = blk & 63;
    int n0 = blk * 64;
    int l0 = g * 64;
    int tid = threadIdx.x;

    for (int idx = tid; idx < DI*DS; idx += 256)
        Hs[(idx >> 4)*17 + (idx & 15)] = g_H[(size_t)blk*DI*DS + idx];
    for (int idx = tid; idx < 64*DS; idx += 256)
        Cs[idx] = g_Cm[(size_t)n0*DS + idx];
    if (tid < DI) {
        a0s[tid] = g_A[tid*DS];
        chs[tid] = (float)g_chain[tid];
    }
    __syncthreads();

    // correction + gating -> ysT[d][tok]; float4 over d
    for (int idx = tid; idx < 64*32; idx += 256) {
        int tok = idx >> 5, d4 = (idx & 31) * 4;
        size_t gi = (size_t)(n0+tok)*DI + d4;
        float4 cd4 = *(const float4*)&g_cd[gi];
        float4 pg4 = *(const float4*)&g_pg[gi];
        float4 sz4 = *(const float4*)&g_z [gi];
        const float* cdp = (const float*)&cd4;
        const float* pgp = (const float*)&pg4;
        const float* szp = (const float*)&sz4;
        #pragma unroll
        for (int k = 0; k < 4; ++k) {
            int d = d4 + k;
            float cdv = cdp[k];
            float y   = pgp[k];
            if (chs[d] != 0.f) {
                float q = __expf(a0s[d] * cdv);
                float poly = Cs[tok*16 + 15] * Hs[d*17 + 15];
                #pragma unroll
                for (int s = 14; s >= 0; --s)
                    poly = fmaf(q, poly, Cs[tok*16 + s] * Hs[d*17 + s]);
                y += q * poly;
            } else {
                #pragma unroll
                for (int s = 0; s < DS; ++s)
                    y += Cs[tok*16 + s] * __expf(g_A[d*DS + s]*cdv) * Hs[d*17 + s];
            }
            ysT[d*68 + tok] = y * szp[k];
        }
    }
    __syncthreads();

    // out_proj GEMM [64c x 64tok x 128K]; weights from global g_WoT (L2)
    int cg = tid >> 4, tg = tid & 15;
    int c0 = cg*4, t0 = tg*4;
    float acc[4][4] = {};
    #pragma unroll 8
    for (int d = 0; d < DI; ++d) {
        float4 av = *(const float4*)&ysT[d*68 + t0];
        float4 wv = __ldg((const float4*)&g_WoT[d*CH + c0]);
        acc[0][0] += wv.x*av.x; acc[0][1] += wv.x*av.y; acc[0][2] += wv.x*av.z; acc[0][3] += wv.x*av.w;
        acc[1][0] += wv.y*av.x; acc[1][1] += wv.y*av.y; acc[1][2] += wv.y*av.z; acc[1][3] += wv.y*av.w;
        acc[2][0] += wv.z*av.x; acc[2][1] += wv.z*av.y; acc[2][2] += wv.z*av.z; acc[2][3] += wv.z*av.w;
        acc[3][0] += wv.w*av.x; acc[3][1] += wv.w*av.y; acc[3][2] += wv.w*av.z; acc[3][3] += wv.w*av.w;
    }
    float4 sj[4];
    #pragma unroll
    for (int j = 0; j < 4; ++j)
        sj[j] = *(const float4*)&g_seq[(size_t)(n0 + t0 + j)*CH + c0];
    #pragma unroll
    for (int i = 0; i < 4; ++i) {
        float4 ov;
        ov.x = acc[i][0] + ((const float*)&sj[0])[i];
        ov.y = acc[i][1] + ((const float*)&sj[1])[i];
        ov.z = acc[i][2] + ((const float*)&sj[2])[i];
        ov.w = acc[i][3] + ((const float*)&sj[3])[i];
        *(float4*)&out[((size_t)(b*CH + c0 + i))*LSEQ + l0 + t0] = ov;
    }
}

// ---------------- launch --------------------------------------------------
extern "C" void kernel_launch(void* const* d_in, const int* in_sizes, int n_in,
                              void* d_out, int out_size) {
    const float* x       = (const float*)d_in[0];
    const float* dwh_w   = (const float*)d_in[1];
    const float* dwh_b   = (const float*)d_in[2];
    const float* dww_w   = (const float*)d_in[3];
    const float* dww_b   = (const float*)d_in[4];
    const float* conv_w  = (const float*)d_in[5];
    const float* conv_b  = (const float*)d_in[6];
    const float* bn_g    = (const float*)d_in[7];
    const float* bn_b    = (const float*)d_in[8];
    const float* bn_m    = (const float*)d_in[9];
    const float* bn_v    = (const float*)d_in[10];
    const float* ln_g    = (const float*)d_in[11];
    const float* ln_b    = (const float*)d_in[12];
    const float* in_proj = (const float*)d_in[13];
    const float* convd_w = (const float*)d_in[14];
    const float* convd_b = (const float*)d_in[15];
    const float* x_proj  = (const float*)d_in[16];
    const float* dt_w    = (const float*)d_in[17];
    const float* dt_b    = (const float*)d_in[18];
    const float* A_log   = (const float*)d_in[19];
    const float* Dp      = (const float*)d_in[20];
    const float* out_w   = (const float*)d_in[21];
    float* out = (float*)d_out;

    cudaFuncSetAttribute(k_fuse1, cudaFuncAttributeMaxDynamicSharedMemorySize, 69120);
    cudaFuncSetAttribute(k_fuse2, cudaFuncAttributeMaxDynamicSharedMemorySize, 43264);
    cudaFuncSetAttribute(k_fuse4, cudaFuncAttributeMaxDynamicSharedMemorySize, 48640);

    k_fuse1<<<BZ*HH, 256, 69120>>>(x, dwh_w, dwh_b, dww_w, dww_b, conv_w, conv_b,
                                   bn_g, bn_b, bn_m, bn_v, ln_g, ln_b, in_proj, A_log, out_w);
    k_fuse2<<<BZ*GCH, 256, 43264>>>(convd_w, convd_b, x_proj, dt_w, dt_b, Dp);
    k_comb<<<64, 128>>>();
    k_fuse4<<<BZ*GCH, 256, 48640>>>(out);
}

// round 12
// speedup vs baseline: 1.0108x; 1.0108x over previous
#include <cuda_runtime.h>
#include <math.h>

#define BZ   4
#define CH   64
#define HH   64
#define WW   64
#define LSEQ (HH*WW)      // 4096
#define NT   (BZ*LSEQ)    // 16384
#define DI   128
#define DS   16
#define DTR  4
#define GCH  64           // chunks per batch
#define TCH  (LSEQ/GCH)   // 64 steps per chunk

// ---------------- scratch (device globals; no allocation) ----------------
__device__ float g_seq[NT*CH];
__device__ float g_xm [NT*DI];
__device__ float g_z  [NT*DI];     // holds silu(z)
__device__ float g_Cm [NT*DS];
__device__ float g_pg [NT*DI];     // yl + xc*Dp
__device__ float g_cd [NT*DI];
__device__ float g_E  [BZ*GCH*DI*DS];
__device__ float g_P  [BZ*GCH*DI*DS];
__device__ float g_H  [BZ*GCH*DI*DS];
__device__ float g_A  [DI*DS];
__device__ float g_WoT[DI*CH];     // out_proj weight transposed [d][c]
__device__ int   g_chain[DI];

__device__ __forceinline__ float siluf(float v) { return v / (1.f + __expf(-v)); }

// ======== K1: axial DW + 1x1 conv + BN + ReLU + LN + in_proj GEMM ========
// dyn smem: t[64][68] | r[64][68] | wB (8576 floats)
__global__ __launch_bounds__(256) void k_fuse1(
        const float* __restrict__ x,
        const float* __restrict__ dwhw, const float* __restrict__ dwhb,
        const float* __restrict__ dwww, const float* __restrict__ dwwb,
        const float* __restrict__ convw, const float* __restrict__ convb,
        const float* __restrict__ bng, const float* __restrict__ bnb,
        const float* __restrict__ bnm, const float* __restrict__ bnv,
        const float* __restrict__ lng, const float* __restrict__ lnb,
        const float* __restrict__ Win, const float* __restrict__ A_log,
        const float* __restrict__ Wout) {
    extern __shared__ __align__(16) float sm1[];
    float* t  = sm1;               // [64][68]
    float* r  = sm1 + 64*68;       // [64][68]
    float* wB = sm1 + 2*64*68;     // 8576 floats
    __shared__ float mu[WW], rs[WW];
    __shared__ float sc[CH], sh[CH];
    int blk = blockIdx.x;
    int b = blk >> 6, h = blk & 63;
    int tid = threadIdx.x;

    if (blk == 0 && tid < DI) {
        int d = tid;
        float a0 = -expf(A_log[d*DS + 0]);
        int ok = 1;
        for (int s = 0; s < DS; ++s) {
            float a = -expf(A_log[d*DS + s]);
            g_A[d*DS + s] = a;
            if (fabsf(a - (float)(s+1)*a0) > 1e-3f*fabsf(a) + 1e-6f) ok = 0;
        }
        g_chain[d] = ok;
    }
    if (blk == 1) {
        for (int idx = tid; idx < DI*CH; idx += 256) {
            int c = idx & 63, d = idx >> 6;
            g_WoT[d*CH + c] = Wout[c*DI + d];
        }
    }

    if (tid < CH) {
        float s = bng[tid] * rsqrtf(bnv[tid] + 1e-5f);
        sc[tid] = s;
        sh[tid] = (convb[tid] - bnm[tid]) * s + bnb[tid];
    }
    const float* xb = x + (size_t)b*CH*LSEQ;
    for (int idx = tid; idx < CH*WW; idx += 256) {
        int c = idx >> 6, w = idx & 63;
        const float* xr = xb + c*LSEQ + h*WW;
        float xv = xr[w];
        float up = (h > 0)    ? xr[w - WW] : 0.f;
        float dn = (h < HH-1) ? xr[w + WW] : 0.f;
        float lf = (w > 0)    ? xr[w - 1]  : 0.f;
        float rt = (w < WW-1) ? xr[w + 1]  : 0.f;
        float v = xv
            + dwhw[c*3+0]*up + dwhw[c*3+1]*xv + dwhw[c*3+2]*dn + dwhb[c]
            + dwww[c*3+0]*lf + dwww[c*3+1]*xv + dwww[c*3+2]*rt + dwwb[c];
        t[c*68 + w] = v;
    }
    __syncthreads();

    int cg = tid >> 4, tg = tid & 15;
    int co0 = cg * 4, w0 = tg * 4;
    {
        float acc[4][4] = {};
        #pragma unroll 4
        for (int ci = 0; ci < CH; ++ci) {
            float4 av = *(const float4*)&t[ci*68 + w0];
            float wv0 = __ldg(&convw[(co0+0)*CH + ci]);
            float wv1 = __ldg(&convw[(co0+1)*CH + ci]);
            float wv2 = __ldg(&convw[(co0+2)*CH + ci]);
            float wv3 = __ldg(&convw[(co0+3)*CH + ci]);
            acc[0][0] += wv0*av.x; acc[0][1] += wv0*av.y; acc[0][2] += wv0*av.z; acc[0][3] += wv0*av.w;
            acc[1][0] += wv1*av.x; acc[1][1] += wv1*av.y; acc[1][2] += wv1*av.z; acc[1][3] += wv1*av.w;
            acc[2][0] += wv2*av.x; acc[2][1] += wv2*av.y; acc[2][2] += wv2*av.z; acc[2][3] += wv2*av.w;
            acc[3][0] += wv3*av.x; acc[3][1] += wv3*av.y; acc[3][2] += wv3*av.z; acc[3][3] += wv3*av.w;
        }
        #pragma unroll
        for (int i = 0; i < 4; ++i)
            #pragma unroll
            for (int j = 0; j < 4; ++j) {
                float v = acc[i][j]*sc[co0+i] + sh[co0+i];
                r[(co0+i)*68 + w0+j] = fmaxf(v, 0.f);
            }
    }
    __syncthreads();

    if (tid < WW) {
        float m = 0.f;
        for (int c = 0; c < CH; ++c) m += r[c*68 + tid];
        m *= (1.f/CH);
        float v = 0.f;
        for (int c = 0; c < CH; ++c) { float dd = r[c*68 + tid] - m; v += dd*dd; }
        v *= (1.f/CH);
        mu[tid] = m; rs[tid] = rsqrtf(v + 1e-5f);
    }
    __syncthreads();

    int n0 = b*LSEQ + h*WW;
    for (int idx = tid; idx < CH*WW; idx += 256) {
        int w = idx >> 6, c = idx & 63;
        float rv = r[c*68 + w];
        g_seq[(size_t)(n0+w)*CH + c] = rv;
        r[c*68 + w] = (rv - mu[w]) * rs[w] * lng[c] + lnb[c];
    }

    int oo0 = cg*4, t0 = tg*4;
    for (int chunk = 0; chunk < 2; ++chunk) {
        int o0 = chunk * 128;
        __syncthreads();
        for (int idx = tid; idx < 128*CH; idx += 256) {
            int oo = idx >> 6, c = idx & 63;
            wB[c*132 + oo] = Win[(o0+oo)*CH + c];
        }
        __syncthreads();
        float acc[8][4] = {};
        #pragma unroll 2
        for (int ci = 0; ci < CH; ++ci) {
            float4 av = *(const float4*)&r[ci*68 + t0];
            float4 u  = *(const float4*)&wB[ci*132 + oo0];
            float4 v  = *(const float4*)&wB[ci*132 + oo0 + 64];
            acc[0][0] += u.x*av.x; acc[0][1] += u.x*av.y; acc[0][2] += u.x*av.z; acc[0][3] += u.x*av.w;
            acc[1][0] += u.y*av.x; acc[1][1] += u.y*av.y; acc[1][2] += u.y*av.z; acc[1][3] += u.y*av.w;
            acc[2][0] += u.z*av.x; acc[2][1] += u.z*av.y; acc[2][2] += u.z*av.z; acc[2][3] += u.z*av.w;
            acc[3][0] += u.w*av.x; acc[3][1] += u.w*av.y; acc[3][2] += u.w*av.z; acc[3][3] += u.w*av.w;
            acc[4][0] += v.x*av.x; acc[4][1] += v.x*av.y; acc[4][2] += v.x*av.z; acc[4][3] += v.x*av.w;
            acc[5][0] += v.y*av.x; acc[5][1] += v.y*av.y; acc[5][2] += v.y*av.z; acc[5][3] += v.y*av.w;
            acc[6][0] += v.z*av.x; acc[6][1] += v.z*av.y; acc[6][2] += v.z*av.z; acc[6][3] += v.z*av.w;
            acc[7][0] += v.w*av.x; acc[7][1] += v.w*av.y; acc[7][2] += v.w*av.z; acc[7][3] += v.w*av.w;
        }
        __syncthreads();
        #pragma unroll
        for (int i = 0; i < 4; ++i)
            #pragma unroll
            for (int j = 0; j < 4; ++j) {
                wB[(oo0+i)*67 + t0+j]    = acc[i][j];
                wB[(oo0+64+i)*67 + t0+j] = acc[4+i][j];
            }
        __syncthreads();
        for (int idx = tid; idx < 128*64; idx += 256) {
            int tok = idx >> 7, oo = idx & 127;
            float vv = wB[oo*67 + tok];
            int n = n0 + tok;
            if (chunk == 0) g_xm[(size_t)n*DI + oo] = vv;
            else            g_z [(size_t)n*DI + oo] = siluf(vv);   // pre-gated
        }
    }
}

// ======== K2: conv1d+SiLU + x_proj + dt + local chunk scan (R9 struct) ===
// dyn smem: xmS[67][132] | xcS[64][129] | dbc[64][40]
#define XM_PITCH 132
#define XC_PITCH 129
__global__ __launch_bounds__(256) void k_fuse2(
        const float* __restrict__ cw, const float* __restrict__ cb,
        const float* __restrict__ xpw,
        const float* __restrict__ dtpw, const float* __restrict__ dtpb,
        const float* __restrict__ Dp) {
    extern __shared__ __align__(16) float sm[];
    float* xmS = sm;                      // 67*132 = 8844 (later: dt rows, then E/P staging)
    float* xcS = sm + 8844;               // 64*129 = 8256
    float* dbc = sm + 8844 + 8256;        // 64*40  = 2560
    int blk = blockIdx.x;                 // b*64 + g
    int g = blk & 63;
    int tid = threadIdx.x;
    int n0 = blk * TCH;

    // phase A: load xm tile with 3-token halo, compute xc = silu(conv1d)
    for (int idx = tid; idx < 67*DI; idx += 256) {
        int i = idx >> 7, d = idx & 127;
        float v = 0.f;
        if (g > 0 || i >= 3) v = g_xm[(size_t)(n0 - 3 + i)*DI + d];
        xmS[i*XM_PITCH + d] = v;
    }
    __syncthreads();
    for (int idx = tid; idx < 64*DI; idx += 256) {
        int tok = idx >> 7, d = idx & 127;
        float acc = __ldg(&cb[d]);
        #pragma unroll
        for (int k = 0; k < 4; ++k)
            acc += __ldg(&cw[d*4 + k]) * xmS[(tok + k)*XM_PITCH + d];
        xcS[tok*XC_PITCH + d] = siluf(acc);
    }
    __syncthreads();

    // phase B: dbc = xc @ xpw^T   (36 outs x 64 toks x 128 K)
    int eg = tid >> 4, tg = tid & 15;
    if (eg < 9) {
        int e0 = eg*4, t0 = tg*4;
        float acc[4][4] = {};
        #pragma unroll 4
        for (int ci = 0; ci < DI; ++ci) {
            float w0_ = __ldg(&xpw[(e0+0)*DI + ci]);
            float w1_ = __ldg(&xpw[(e0+1)*DI + ci]);
            float w2_ = __ldg(&xpw[(e0+2)*DI + ci]);
            float w3_ = __ldg(&xpw[(e0+3)*DI + ci]);
            float a0_ = xcS[(t0+0)*XC_PITCH + ci];
            float a1_ = xcS[(t0+1)*XC_PITCH + ci];
            float a2_ = xcS[(t0+2)*XC_PITCH + ci];
            float a3_ = xcS[(t0+3)*XC_PITCH + ci];
            acc[0][0] += w0_*a0_; acc[0][1] += w0_*a1_; acc[0][2] += w0_*a2_; acc[0][3] += w0_*a3_;
            acc[1][0] += w1_*a0_; acc[1][1] += w1_*a1_; acc[1][2] += w1_*a2_; acc[1][3] += w1_*a3_;
            acc[2][0] += w2_*a0_; acc[2][1] += w2_*a1_; acc[2][2] += w2_*a2_; acc[2][3] += w2_*a3_;
            acc[3][0] += w3_*a0_; acc[3][1] += w3_*a1_; acc[3][2] += w3_*a2_; acc[3][3] += w3_*a3_;
        }
        #pragma unroll
        for (int i = 0; i < 4; ++i)
            #pragma unroll
            for (int j = 0; j < 4; ++j) dbc[(t0+j)*40 + e0+i] = acc[i][j];
    }
    __syncthreads();

    // phase C: dt = softplus(dbc[:,0:4] @ dtpw^T + b) -> overwrite xmS rows 0..63
    for (int idx = tid; idx < 64*DI; idx += 256) {
        int tok = idx >> 7, d = idx & 127;
        float raw = __ldg(&dtpb[d]);
        #pragma unroll
        for (int rr = 0; rr < DTR; ++rr) raw += dbc[tok*40 + rr] * __ldg(&dtpw[d*DTR + rr]);
        float dt = (raw > 20.f) ? raw : log1pf(__expf(raw));
        xmS[tok*XM_PITCH + d] = dt;
    }
    // export C for K4
    for (int idx = tid; idx < 64*DS; idx += 256) {
        int tok = idx >> 4, s = idx & 15;
        g_Cm[(size_t)(n0+tok)*DS + s] = dbc[tok*40 + 20 + s];
    }
    __syncthreads();

    // phase D: local scan (zero-init), paired lanes: thread = (d, half)
    int d = tid >> 1, half = tid & 1;
    float hreg[8];
    float cd = 0.f;
    {
        float a0 = g_A[d*DS];
        bool chain = (g_chain[d] != 0);
        float As[8];
        #pragma unroll
        for (int j = 0; j < 8; ++j) As[j] = g_A[d*DS + half*8 + j];
        #pragma unroll
        for (int j = 0; j < 8; ++j) hreg[j] = 0.f;
        float dpv = __ldg(&Dp[d]);
        const float* Bp = dbc + 4 + half*8;
        const float* Cp = dbc + 20 + half*8;

        if (chain) {
            for (int st = 0; st < TCH; ++st) {
                float dtv = xmS[st*XM_PITCH + d];
                float xcv = xcS[st*XC_PITCH + d];
                float dxv = dtv * xcv;
                cd += dtv;
                float e1 = __expf(dtv * a0);
                float e2 = e1*e1, e3 = e2*e1, e4 = e2*e2;
                float e5 = e4*e1, e6 = e4*e2, e7 = e4*e3, e8 = e4*e4;
                float base = half ? e8 : 1.f;
                float p0 = base*e1, p1 = base*e2, p2 = base*e3, p3 = base*e4;
                float p4 = base*e5, p5 = base*e6, p6 = base*e7, p7 = base*e8;
                const float* Bs = Bp + st*40;
                const float* Cs_ = Cp + st*40;
                float y;
                hreg[0] = p0*hreg[0] + dxv*Bs[0];  y  = hreg[0]*Cs_[0];
                hreg[1] = p1*hreg[1] + dxv*Bs[1];  y += hreg[1]*Cs_[1];
                hreg[2] = p2*hreg[2] + dxv*Bs[2];  y += hreg[2]*Cs_[2];
                hreg[3] = p3*hreg[3] + dxv*Bs[3];  y += hreg[3]*Cs_[3];
                hreg[4] = p4*hreg[4] + dxv*Bs[4];  y += hreg[4]*Cs_[4];
                hreg[5] = p5*hreg[5] + dxv*Bs[5];  y += hreg[5]*Cs_[5];
                hreg[6] = p6*hreg[6] + dxv*Bs[6];  y += hreg[6]*Cs_[6];
                hreg[7] = p7*hreg[7] + dxv*Bs[7];  y += hreg[7]*Cs_[7];
                y += __shfl_xor_sync(0xffffffffu, y, 1);
                if (half == 0) {
                    size_t gi = (size_t)(n0+st)*DI + d;
                    g_pg[gi] = y + xcv*dpv; g_cd[gi] = cd;
                }
            }
        } else {
            for (int st = 0; st < TCH; ++st) {
                float dtv = xmS[st*XM_PITCH + d];
                float xcv = xcS[st*XC_PITCH + d];
                float dxv = dtv * xcv;
                cd += dtv;
                const float* Bs = Bp + st*40;
                const float* Cs_ = Cp + st*40;
                float y = 0.f;
                #pragma unroll
                for (int j = 0; j < 8; ++j) {
                    float dA = __expf(dtv * As[j]);
                    hreg[j] = dA*hreg[j] + dxv*Bs[j];
                    y += hreg[j]*Cs_[j];
                }
                y += __shfl_xor_sync(0xffffffffu, y, 1);
                if (half == 0) {
                    size_t gi = (size_t)(n0+st)*DI + d;
                    g_pg[gi] = y + xcv*dpv; g_cd[gi] = cd;
                }
            }
        }
    }
    __syncthreads();   // all dt/xc reads done before staging overwrites xmS
    {
        float* stgE = xmS;          // 2048 floats
        float* stgP = xmS + 2048;   // 2048 floats
        float a0 = g_A[d*DS];
        bool chain = (g_chain[d] != 0);
        int sb = d*DS + half*8;
        #pragma unroll
        for (int j = 0; j < 8; ++j) stgE[sb + j] = hreg[j];
        if (chain) {
            float q = __expf(a0 * cd);
            float q2 = q*q, q3 = q2*q, q4 = q2*q2;
            float q5 = q4*q, q6 = q4*q2, q7 = q4*q3, q8 = q4*q4;
            float base = half ? q8 : 1.f;
            stgP[sb+0] = base*q;  stgP[sb+1] = base*q2;
            stgP[sb+2] = base*q3; stgP[sb+3] = base*q4;
            stgP[sb+4] = base*q5; stgP[sb+5] = base*q6;
            stgP[sb+6] = base*q7; stgP[sb+7] = base*q8;
        } else {
            #pragma unroll
            for (int j = 0; j < 8; ++j)
                stgP[sb + j] = __expf(g_A[d*DS + half*8 + j]*cd);
        }
    }
    __syncthreads();
    for (int idx = tid; idx < DI*DS; idx += 256) {
        g_E[(size_t)blk*DI*DS + idx] = xmS[idx];
        g_P[(size_t)blk*DI*DS + idx] = xmS[2048 + idx];
    }
}

// ---------------- K3: sequential chunk-state combine (pipelined) ---------
__global__ __launch_bounds__(128) void k_comb() {
    int i = blockIdx.x * 128 + threadIdx.x;    // 8192 = BZ*DI*DS
    int b = i >> 11, r = i & 2047;
    size_t base = (size_t)b*GCH*(DI*DS) + r;

    float Pb[8], Eb[8];
    #pragma unroll
    for (int j = 0; j < 8; ++j) {
        Pb[j] = g_P[base + (size_t)j*(DI*DS)];
        Eb[j] = g_E[base + (size_t)j*(DI*DS)];
    }
    float h = 0.f;
    #pragma unroll
    for (int grp = 0; grp < 8; ++grp) {
        float Pn[8], En[8];
        if (grp < 7) {
            #pragma unroll
            for (int j = 0; j < 8; ++j) {
                size_t o = base + (size_t)((grp+1)*8 + j)*(DI*DS);
                Pn[j] = g_P[o];
                En[j] = g_E[o];
            }
        }
        #pragma unroll
        for (int j = 0; j < 8; ++j) {
            g_H[base + (size_t)(grp*8 + j)*(DI*DS)] = h;
            h = fmaf(Pb[j], h, Eb[j]);
        }
        if (grp < 7) {
            #pragma unroll
            for (int j = 0; j < 8; ++j) { Pb[j] = Pn[j]; Eb[j] = En[j]; }
        }
    }
}

// ======== K4: correction + gating + out_proj + residual + NCHW ===========
// Token-split: grid = BZ*GCH*2 blocks, each does 32 tokens (30KB smem).
// dyn smem: ysT[128][36] | Hs[128][17] | Cs[32][16] | a0s | chs
#define YS_PITCH 36
__global__ __launch_bounds__(256, 4) void k_fuse4(float* __restrict__ out) {
    extern __shared__ __align__(16) float sm[];
    float* ysT  = sm;                    // [128][36]  4608 floats
    float* Hs   = sm + 4608;             // [128][17]  2176
    float* Cs   = sm + 6784;             // [32][16]   512
    float* a0s  = sm + 7296;             // [128]
    float* chs  = sm + 7424;             // [128]
    int blk = blockIdx.x;                // (b*64 + g)*2 + ht
    int ht  = blk & 1;
    int bg  = blk >> 1;                  // b*64 + g
    int b = bg >> 6, g = bg & 63;
    int n0 = bg * 64 + ht * 32;          // first token of this half-tile
    int l0 = g * 64 + ht * 32;
    int tid = threadIdx.x;

    for (int idx = tid; idx < DI*DS; idx += 256)
        Hs[(idx >> 4)*17 + (idx & 15)] = g_H[(size_t)bg*DI*DS + idx];
    for (int idx = tid; idx < 32*DS; idx += 256)
        Cs[idx] = g_Cm[(size_t)n0*DS + idx];
    if (tid < DI) {
        a0s[tid] = g_A[tid*DS];
        chs[tid] = (float)g_chain[tid];
    }
    __syncthreads();

    // correction + gating -> ysT[d][tok]; float4 over d
    for (int idx = tid; idx < 32*32; idx += 256) {
        int tok = idx >> 5, d4 = (idx & 31) * 4;
        size_t gi = (size_t)(n0+tok)*DI + d4;
        float4 cd4 = *(const float4*)&g_cd[gi];
        float4 pg4 = *(const float4*)&g_pg[gi];
        float4 sz4 = *(const float4*)&g_z [gi];
        const float* cdp = (const float*)&cd4;
        const float* pgp = (const float*)&pg4;
        const float* szp = (const float*)&sz4;
        #pragma unroll
        for (int k = 0; k < 4; ++k) {
            int d = d4 + k;
            float cdv = cdp[k];
            float y   = pgp[k];
            if (chs[d] != 0.f) {
                float q = __expf(a0s[d] * cdv);
                float poly = Cs[tok*16 + 15] * Hs[d*17 + 15];
                #pragma unroll
                for (int s = 14; s >= 0; --s)
                    poly = fmaf(q, poly, Cs[tok*16 + s] * Hs[d*17 + s]);
                y += q * poly;
            } else {
                #pragma unroll
                for (int s = 0; s < DS; ++s)
                    y += Cs[tok*16 + s] * __expf(g_A[d*DS + s]*cdv) * Hs[d*17 + s];
            }
            ysT[d*YS_PITCH + tok] = y * szp[k];
        }
    }
    __syncthreads();

    // out_proj GEMM [64c x 32tok x 128K]; 4c x 2tok microtile
    int cg = tid >> 4, tg = tid & 15;
    int c0 = cg*4, t0 = tg*2;
    float acc[4][2] = {};
    #pragma unroll 8
    for (int d = 0; d < DI; ++d) {
        float2 av = *(const float2*)&ysT[d*YS_PITCH + t0];
        float4 wv = __ldg((const float4*)&g_WoT[d*CH + c0]);
        acc[0][0] += wv.x*av.x; acc[0][1] += wv.x*av.y;
        acc[1][0] += wv.y*av.x; acc[1][1] += wv.y*av.y;
        acc[2][0] += wv.z*av.x; acc[2][1] += wv.z*av.y;
        acc[3][0] += wv.w*av.x; acc[3][1] += wv.w*av.y;
    }
    float4 s0 = *(const float4*)&g_seq[(size_t)(n0 + t0 + 0)*CH + c0];
    float4 s1 = *(const float4*)&g_seq[(size_t)(n0 + t0 + 1)*CH + c0];
    const float* s0p = (const float*)&s0;
    const float* s1p = (const float*)&s1;
    #pragma unroll
    for (int i = 0; i < 4; ++i) {
        float2 ov;
        ov.x = acc[i][0] + s0p[i];
        ov.y = acc[i][1] + s1p[i];
        *(float2*)&out[((size_t)(b*CH + c0 + i))*LSEQ + l0 + t0] = ov;
    }
}

// ---------------- launch --------------------------------------------------
extern "C" void kernel_launch(void* const* d_in, const int* in_sizes, int n_in,
                              void* d_out, int out_size) {
    const float* x       = (const float*)d_in[0];
    const float* dwh_w   = (const float*)d_in[1];
    const float* dwh_b   = (const float*)d_in[2];
    const float* dww_w   = (const float*)d_in[3];
    const float* dww_b   = (const float*)d_in[4];
    const float* conv_w  = (const float*)d_in[5];
    const float* conv_b  = (const float*)d_in[6];
    const float* bn_g    = (const float*)d_in[7];
    const float* bn_b    = (const float*)d_in[8];
    const float* bn_m    = (const float*)d_in[9];
    const float* bn_v    = (const float*)d_in[10];
    const float* ln_g    = (const float*)d_in[11];
    const float* ln_b    = (const float*)d_in[12];
    const float* in_proj = (const float*)d_in[13];
    const float* convd_w = (const float*)d_in[14];
    const float* convd_b = (const float*)d_in[15];
    const float* x_proj  = (const float*)d_in[16];
    const float* dt_w    = (const float*)d_in[17];
    const float* dt_b    = (const float*)d_in[18];
    const float* A_log   = (const float*)d_in[19];
    const float* Dp      = (const float*)d_in[20];
    const float* out_w   = (const float*)d_in[21];
    float* out = (float*)d_out;

    cudaFuncSetAttribute(k_fuse1, cudaFuncAttributeMaxDynamicSharedMemorySize, 69120);
    cudaFuncSetAttribute(k_fuse2, cudaFuncAttributeMaxDynamicSharedMemorySize, 78640);
    cudaFuncSetAttribute(k_fuse4, cudaFuncAttributeMaxDynamicSharedMemorySize, 30208);

    k_fuse1<<<BZ*HH, 256, 69120>>>(x, dwh_w, dwh_b, dww_w, dww_b, conv_w, conv_b,
                                   bn_g, bn_b, bn_m, bn_v, ln_g, ln_b, in_proj, A_log, out_w);
    k_fuse2<<<BZ*GCH, 256, 78640>>>(convd_w, convd_b, x_proj, dt_w, dt_b, Dp);
    k_comb<<<64, 128>>>();
    k_fuse4<<<BZ*GCH*2, 256, 30208>>>(out);
}

// round 15
// speedup vs baseline: 1.1239x; 1.1119x over previous
#include <cuda_runtime.h>
#include <math.h>

#define BZ   4
#define CH   64
#define HH   64
#define WW   64
#define LSEQ (HH*WW)      // 4096
#define NT   (BZ*LSEQ)    // 16384
#define DI   128
#define DS   16
#define DTR  4
#define GCH  64           // chunks per batch
#define TCH  (LSEQ/GCH)   // 64 steps per chunk

// ---------------- scratch (device globals; no allocation) ----------------
__device__ float g_seq[NT*CH];
__device__ float g_xm [NT*DI];
__device__ float g_z  [NT*DI];     // holds silu(z)
__device__ float g_Cm [NT*DS];
__device__ float g_pg [NT*DI];     // yl + xc*Dp
__device__ float g_cd [NT*DI];
__device__ float g_E  [BZ*GCH*DI*DS];
__device__ float g_P  [BZ*GCH*DI*DS];
__device__ float g_H  [BZ*GCH*DI*DS];
__device__ float g_A  [DI*DS];
__device__ float g_WoT[DI*CH];     // out_proj weight transposed [d][c]
__device__ int   g_chain[DI];

__device__ __forceinline__ float siluf(float v) { return v / (1.f + __expf(-v)); }

// ======== K1: axial DW + 1x1 conv + BN + ReLU + LN + in_proj GEMM ========
// (block 0 initializes g_A/g_chain; block 1 transposes Wout -> g_WoT)
// dyn smem: t[64][68] | r[64][68] | wB (8576 floats)
__global__ __launch_bounds__(256) void k_fuse1(
        const float* __restrict__ x,
        const float* __restrict__ dwhw, const float* __restrict__ dwhb,
        const float* __restrict__ dwww, const float* __restrict__ dwwb,
        const float* __restrict__ convw, const float* __restrict__ convb,
        const float* __restrict__ bng, const float* __restrict__ bnb,
        const float* __restrict__ bnm, const float* __restrict__ bnv,
        const float* __restrict__ lng, const float* __restrict__ lnb,
        const float* __restrict__ Win, const float* __restrict__ A_log,
        const float* __restrict__ Wout) {
    extern __shared__ __align__(16) float sm1[];
    float* t  = sm1;               // [64][68]
    float* r  = sm1 + 64*68;       // [64][68]
    float* wB = sm1 + 2*64*68;     // 8576 floats
    __shared__ float mu[WW], rs[WW];
    __shared__ float sc[CH], sh[CH];
    int blk = blockIdx.x;
    int b = blk >> 6, h = blk & 63;
    int tid = threadIdx.x;

    if (blk == 0 && tid < DI) {
        int d = tid;
        float a0 = -expf(A_log[d*DS + 0]);
        int ok = 1;
        for (int s = 0; s < DS; ++s) {
            float a = -expf(A_log[d*DS + s]);
            g_A[d*DS + s] = a;
            if (fabsf(a - (float)(s+1)*a0) > 1e-3f*fabsf(a) + 1e-6f) ok = 0;
        }
        g_chain[d] = ok;
    }
    if (blk == 1) {
        for (int idx = tid; idx < DI*CH; idx += 256) {
            int c = idx & 63, d = idx >> 6;
            g_WoT[d*CH + c] = Wout[c*DI + d];
        }
    }

    if (tid < CH) {
        float s = bng[tid] * rsqrtf(bnv[tid] + 1e-5f);
        sc[tid] = s;
        sh[tid] = (convb[tid] - bnm[tid]) * s + bnb[tid];
    }
    const float* xb = x + (size_t)b*CH*LSEQ;
    for (int idx = tid; idx < CH*WW; idx += 256) {
        int c = idx >> 6, w = idx & 63;
        const float* xr = xb + c*LSEQ + h*WW;
        float xv = xr[w];
        float up = (h > 0)    ? xr[w - WW] : 0.f;
        float dn = (h < HH-1) ? xr[w + WW] : 0.f;
        float lf = (w > 0)    ? xr[w - 1]  : 0.f;
        float rt = (w < WW-1) ? xr[w + 1]  : 0.f;
        float v = xv
            + dwhw[c*3+0]*up + dwhw[c*3+1]*xv + dwhw[c*3+2]*dn + dwhb[c]
            + dwww[c*3+0]*lf + dwww[c*3+1]*xv + dwww[c*3+2]*rt + dwwb[c];
        t[c*68 + w] = v;
    }
    __syncthreads();

    int cg = tid >> 4, tg = tid & 15;
    int co0 = cg * 4, w0 = tg * 4;
    {
        float acc[4][4] = {};
        #pragma unroll 4
        for (int ci = 0; ci < CH; ++ci) {
            float4 av = *(const float4*)&t[ci*68 + w0];
            float wv0 = __ldg(&convw[(co0+0)*CH + ci]);
            float wv1 = __ldg(&convw[(co0+1)*CH + ci]);
            float wv2 = __ldg(&convw[(co0+2)*CH + ci]);
            float wv3 = __ldg(&convw[(co0+3)*CH + ci]);
            acc[0][0] += wv0*av.x; acc[0][1] += wv0*av.y; acc[0][2] += wv0*av.z; acc[0][3] += wv0*av.w;
            acc[1][0] += wv1*av.x; acc[1][1] += wv1*av.y; acc[1][2] += wv1*av.z; acc[1][3] += wv1*av.w;
            acc[2][0] += wv2*av.x; acc[2][1] += wv2*av.y; acc[2][2] += wv2*av.z; acc[2][3] += wv2*av.w;
            acc[3][0] += wv3*av.x; acc[3][1] += wv3*av.y; acc[3][2] += wv3*av.z; acc[3][3] += wv3*av.w;
        }
        #pragma unroll
        for (int i = 0; i < 4; ++i)
            #pragma unroll
            for (int j = 0; j < 4; ++j) {
                float v = acc[i][j]*sc[co0+i] + sh[co0+i];
                r[(co0+i)*68 + w0+j] = fmaxf(v, 0.f);
            }
    }
    __syncthreads();

    if (tid < WW) {
        float m = 0.f;
        for (int c = 0; c < CH; ++c) m += r[c*68 + tid];
        m *= (1.f/CH);
        float v = 0.f;
        for (int c = 0; c < CH; ++c) { float dd = r[c*68 + tid] - m; v += dd*dd; }
        v *= (1.f/CH);
        mu[tid] = m; rs[tid] = rsqrtf(v + 1e-5f);
    }
    __syncthreads();

    int n0 = b*LSEQ + h*WW;
    for (int idx = tid; idx < CH*WW; idx += 256) {
        int w = idx >> 6, c = idx & 63;
        float rv = r[c*68 + w];
        g_seq[(size_t)(n0+w)*CH + c] = rv;
        r[c*68 + w] = (rv - mu[w]) * rs[w] * lng[c] + lnb[c];
    }

    int oo0 = cg*4, t0 = tg*4;
    for (int chunk = 0; chunk < 2; ++chunk) {
        int o0 = chunk * 128;
        __syncthreads();
        for (int idx = tid; idx < 128*CH; idx += 256) {
            int oo = idx >> 6, c = idx & 63;
            wB[c*132 + oo] = Win[(o0+oo)*CH + c];
        }
        __syncthreads();
        float acc[8][4] = {};
        #pragma unroll 2
        for (int ci = 0; ci < CH; ++ci) {
            float4 av = *(const float4*)&r[ci*68 + t0];
            float4 u  = *(const float4*)&wB[ci*132 + oo0];
            float4 v  = *(const float4*)&wB[ci*132 + oo0 + 64];
            acc[0][0] += u.x*av.x; acc[0][1] += u.x*av.y; acc[0][2] += u.x*av.z; acc[0][3] += u.x*av.w;
            acc[1][0] += u.y*av.x; acc[1][1] += u.y*av.y; acc[1][2] += u.y*av.z; acc[1][3] += u.y*av.w;
            acc[2][0] += u.z*av.x; acc[2][1] += u.z*av.y; acc[2][2] += u.z*av.z; acc[2][3] += u.z*av.w;
            acc[3][0] += u.w*av.x; acc[3][1] += u.w*av.y; acc[3][2] += u.w*av.z; acc[3][3] += u.w*av.w;
            acc[4][0] += v.x*av.x; acc[4][1] += v.x*av.y; acc[4][2] += v.x*av.z; acc[4][3] += v.x*av.w;
            acc[5][0] += v.y*av.x; acc[5][1] += v.y*av.y; acc[5][2] += v.y*av.z; acc[5][3] += v.y*av.w;
            acc[6][0] += v.z*av.x; acc[6][1] += v.z*av.y; acc[6][2] += v.z*av.z; acc[6][3] += v.z*av.w;
            acc[7][0] += v.w*av.x; acc[7][1] += v.w*av.y; acc[7][2] += v.w*av.z; acc[7][3] += v.w*av.w;
        }
        __syncthreads();
        #pragma unroll
        for (int i = 0; i < 4; ++i)
            #pragma unroll
            for (int j = 0; j < 4; ++j) {
                wB[(oo0+i)*67 + t0+j]    = acc[i][j];
                wB[(oo0+64+i)*67 + t0+j] = acc[4+i][j];
            }
        __syncthreads();
        for (int idx = tid; idx < 128*64; idx += 256) {
            int tok = idx >> 7, oo = idx & 127;
            float vv = wB[oo*67 + tok];
            int n = n0 + tok;
            if (chunk == 0) g_xm[(size_t)n*DI + oo] = vv;
            else            g_z [(size_t)n*DI + oo] = siluf(vv);   // pre-gated
        }
    }
}

// ======== K2: conv1d+SiLU + x_proj + dt + local chunk scan (R8 struct) ===
// dyn smem: xmS[67][132] | xcS[64][129] | dbc[64][40]
#define XM_PITCH 132
#define XC_PITCH 129
__global__ __launch_bounds__(256) void k_fuse2(
        const float* __restrict__ cw, const float* __restrict__ cb,
        const float* __restrict__ xpw,
        const float* __restrict__ dtpw, const float* __restrict__ dtpb,
        const float* __restrict__ Dp) {
    extern __shared__ __align__(16) float sm[];
    float* xmS = sm;                      // 67*132 = 8844 (later: dt rows, then E/P staging)
    float* xcS = sm + 8844;               // 64*129 = 8256
    float* dbc = sm + 8844 + 8256;        // 64*40  = 2560
    int blk = blockIdx.x;                 // b*64 + g
    int g = blk & 63;
    int tid = threadIdx.x;
    int n0 = blk * TCH;

    // phase A: load xm tile with 3-token halo, compute xc = silu(conv1d)
    for (int idx = tid; idx < 67*DI; idx += 256) {
        int i = idx >> 7, d = idx & 127;
        float v = 0.f;
        if (g > 0 || i >= 3) v = g_xm[(size_t)(n0 - 3 + i)*DI + d];
        xmS[i*XM_PITCH + d] = v;
    }
    __syncthreads();
    for (int idx = tid; idx < 64*DI; idx += 256) {
        int tok = idx >> 7, d = idx & 127;
        float acc = __ldg(&cb[d]);
        #pragma unroll
        for (int k = 0; k < 4; ++k)
            acc += __ldg(&cw[d*4 + k]) * xmS[(tok + k)*XM_PITCH + d];
        xcS[tok*XC_PITCH + d] = siluf(acc);
    }
    __syncthreads();

    // phase B: dbc = xc @ xpw^T   (36 outs x 64 toks x 128 K)
    int eg = tid >> 4, tg = tid & 15;
    if (eg < 9) {
        int e0 = eg*4, t0 = tg*4;
        float acc[4][4] = {};
        #pragma unroll 4
        for (int ci = 0; ci < DI; ++ci) {
            float w0_ = __ldg(&xpw[(e0+0)*DI + ci]);
            float w1_ = __ldg(&xpw[(e0+1)*DI + ci]);
            float w2_ = __ldg(&xpw[(e0+2)*DI + ci]);
            float w3_ = __ldg(&xpw[(e0+3)*DI + ci]);
            float a0_ = xcS[(t0+0)*XC_PITCH + ci];
            float a1_ = xcS[(t0+1)*XC_PITCH + ci];
            float a2_ = xcS[(t0+2)*XC_PITCH + ci];
            float a3_ = xcS[(t0+3)*XC_PITCH + ci];
            acc[0][0] += w0_*a0_; acc[0][1] += w0_*a1_; acc[0][2] += w0_*a2_; acc[0][3] += w0_*a3_;
            acc[1][0] += w1_*a0_; acc[1][1] += w1_*a1_; acc[1][2] += w1_*a2_; acc[1][3] += w1_*a3_;
            acc[2][0] += w2_*a0_; acc[2][1] += w2_*a1_; acc[2][2] += w2_*a2_; acc[2][3] += w2_*a3_;
            acc[3][0] += w3_*a0_; acc[3][1] += w3_*a1_; acc[3][2] += w3_*a2_; acc[3][3] += w3_*a3_;
        }
        #pragma unroll
        for (int i = 0; i < 4; ++i)
            #pragma unroll
            for (int j = 0; j < 4; ++j) dbc[(t0+j)*40 + e0+i] = acc[i][j];
    }
    __syncthreads();

    // phase C: dt = softplus(dbc[:,0:4] @ dtpw^T + b) -> overwrite xmS rows 0..63
    for (int idx = tid; idx < 64*DI; idx += 256) {
        int tok = idx >> 7, d = idx & 127;
        float raw = __ldg(&dtpb[d]);
        #pragma unroll
        for (int rr = 0; rr < DTR; ++rr) raw += dbc[tok*40 + rr] * __ldg(&dtpw[d*DTR + rr]);
        float dt = (raw > 20.f) ? raw : log1pf(__expf(raw));
        xmS[tok*XM_PITCH + d] = dt;
    }
    // export C for K4
    for (int idx = tid; idx < 64*DS; idx += 256) {
        int tok = idx >> 4, s = idx & 15;
        g_Cm[(size_t)(n0+tok)*DS + s] = dbc[tok*40 + 20 + s];
    }
    __syncthreads();

    // phase D: local scan (zero-init), paired lanes: thread = (d, half)
    int d = tid >> 1, half = tid & 1;
    float hreg[8];
    float cd = 0.f;
    {
        float a0 = g_A[d*DS];
        bool chain = (g_chain[d] != 0);
        float As[8];
        #pragma unroll
        for (int j = 0; j < 8; ++j) As[j] = g_A[d*DS + half*8 + j];
        #pragma unroll
        for (int j = 0; j < 8; ++j) hreg[j] = 0.f;
        float dpv = __ldg(&Dp[d]);
        const float* Bp = dbc + 4 + half*8;
        const float* Cp = dbc + 20 + half*8;

        if (chain) {
            for (int st = 0; st < TCH; ++st) {
                float dtv = xmS[st*XM_PITCH + d];
                float xcv = xcS[st*XC_PITCH + d];
                float dxv = dtv * xcv;
                cd += dtv;
                float e1 = __expf(dtv * a0);
                float e2 = e1*e1, e3 = e2*e1, e4 = e2*e2;
                float e5 = e4*e1, e6 = e4*e2, e7 = e4*e3, e8 = e4*e4;
                float base = half ? e8 : 1.f;
                float p0 = base*e1, p1 = base*e2, p2 = base*e3, p3 = base*e4;
                float p4 = base*e5, p5 = base*e6, p6 = base*e7, p7 = base*e8;
                const float* Bs = Bp + st*40;
                const float* Cs_ = Cp + st*40;
                float y;
                hreg[0] = p0*hreg[0] + dxv*Bs[0];  y  = hreg[0]*Cs_[0];
                hreg[1] = p1*hreg[1] + dxv*Bs[1];  y += hreg[1]*Cs_[1];
                hreg[2] = p2*hreg[2] + dxv*Bs[2];  y += hreg[2]*Cs_[2];
                hreg[3] = p3*hreg[3] + dxv*Bs[3];  y += hreg[3]*Cs_[3];
                hreg[4] = p4*hreg[4] + dxv*Bs[4];  y += hreg[4]*Cs_[4];
                hreg[5] = p5*hreg[5] + dxv*Bs[5];  y += hreg[5]*Cs_[5];
                hreg[6] = p6*hreg[6] + dxv*Bs[6];  y += hreg[6]*Cs_[6];
                hreg[7] = p7*hreg[7] + dxv*Bs[7];  y += hreg[7]*Cs_[7];
                y += __shfl_xor_sync(0xffffffffu, y, 1);
                if (half == 0) {
                    size_t gi = (size_t)(n0+st)*DI + d;
                    g_pg[gi] = y + xcv*dpv; g_cd[gi] = cd;
                }
            }
        } else {
            for (int st = 0; st < TCH; ++st) {
                float dtv = xmS[st*XM_PITCH + d];
                float xcv = xcS[st*XC_PITCH + d];
                float dxv = dtv * xcv;
                cd += dtv;
                const float* Bs = Bp + st*40;
                const float* Cs_ = Cp + st*40;
                float y = 0.f;
                #pragma unroll
                for (int j = 0; j < 8; ++j) {
                    float dA = __expf(dtv * As[j]);
                    hreg[j] = dA*hreg[j] + dxv*Bs[j];
                    y += hreg[j]*Cs_[j];
                }
                y += __shfl_xor_sync(0xffffffffu, y, 1);
                if (half == 0) {
                    size_t gi = (size_t)(n0+st)*DI + d;
                    g_pg[gi] = y + xcv*dpv; g_cd[gi] = cd;
                }
            }
        }
    }
    __syncthreads();   // all dt/xc reads done before staging overwrites xmS
    {
        float* stgE = xmS;          // 2048 floats
        float* stgP = xmS + 2048;   // 2048 floats
        float a0 = g_A[d*DS];
        bool chain = (g_chain[d] != 0);
        int sb = d*DS + half*8;
        #pragma unroll
        for (int j = 0; j < 8; ++j) stgE[sb + j] = hreg[j];
        if (chain) {
            float q = __expf(a0 * cd);
            float q2 = q*q, q3 = q2*q, q4 = q2*q2;
            float q5 = q4*q, q6 = q4*q2, q7 = q4*q3, q8 = q4*q4;
            float base = half ? q8 : 1.f;
            stgP[sb+0] = base*q;  stgP[sb+1] = base*q2;
            stgP[sb+2] = base*q3; stgP[sb+3] = base*q4;
            stgP[sb+4] = base*q5; stgP[sb+5] = base*q6;
            stgP[sb+6] = base*q7; stgP[sb+7] = base*q8;
        } else {
            #pragma unroll
            for (int j = 0; j < 8; ++j)
                stgP[sb + j] = __expf(g_A[d*DS + half*8 + j]*cd);
        }
    }
    __syncthreads();
    for (int idx = tid; idx < DI*DS; idx += 256) {
        g_E[(size_t)blk*DI*DS + idx] = xmS[idx];
        g_P[(size_t)blk*DI*DS + idx] = xmS[2048 + idx];
    }
}

// ---------------- K3: sequential chunk-state combine (pipelined) ---------
__global__ __launch_bounds__(128) void k_comb() {
    int i = blockIdx.x * 128 + threadIdx.x;    // 8192 = BZ*DI*DS
    int b = i >> 11, r = i & 2047;
    size_t base = (size_t)b*GCH*(DI*DS) + r;

    float Pb[8], Eb[8];
    #pragma unroll
    for (int j = 0; j < 8; ++j) {
        Pb[j] = g_P[base + (size_t)j*(DI*DS)];
        Eb[j] = g_E[base + (size_t)j*(DI*DS)];
    }
    float h = 0.f;
    #pragma unroll
    for (int grp = 0; grp < 8; ++grp) {
        float Pn[8], En[8];
        if (grp < 7) {
            #pragma unroll
            for (int j = 0; j < 8; ++j) {
                size_t o = base + (size_t)((grp+1)*8 + j)*(DI*DS);
                Pn[j] = g_P[o];
                En[j] = g_E[o];
            }
        }
        #pragma unroll
        for (int j = 0; j < 8; ++j) {
            g_H[base + (size_t)(grp*8 + j)*(DI*DS)] = h;
            h = fmaf(Pb[j], h, Eb[j]);
        }
        if (grp < 7) {
            #pragma unroll
            for (int j = 0; j < 8; ++j) { Pb[j] = Pn[j]; Eb[j] = En[j]; }
        }
    }
}

// ======== K4: correction + gating + out_proj + residual + NCHW ===========
// Token-split: grid = BZ*GCH*2, 32 tokens per block.
// Thread = (d, token-half): H[d][*] register-resident; Cs broadcast float4.
// dyn smem: ysT[128][34] | wT[128][68] | Cs[32][16]   (54.3KB -> 4 CTAs/SM)
#define YS_PITCH 34
__global__ __launch_bounds__(256, 4) void k_fuse4(float* __restrict__ out) {
    extern __shared__ __align__(16) float sm[];
    float* ysT = sm;                     // [128][34]  4352 floats
    float* wT  = sm + 4352;              // [128][68]  8704 floats
    float* Cs  = sm + 13056;             // [32][16]   512 floats
    int blk = blockIdx.x;                // (b*64 + g)*2 + ht
    int ht  = blk & 1;
    int bg  = blk >> 1;                  // b*64 + g
    int b = bg >> 6, g = bg & 63;
    int n0 = bg * 64 + ht * 32;          // first token of this half-tile
    int l0 = g * 64 + ht * 32;
    int tid = threadIdx.x;

    // load weights (coalesced, conflict-free) and C tile
    for (int idx = tid; idx < DI*CH; idx += 256) {
        int c = idx & 63, d = idx >> 6;
        wT[d*68 + c] = g_WoT[idx];
    }
    for (int idx = tid; idx < 32*DS; idx += 256)
        Cs[idx] = g_Cm[(size_t)n0*DS + idx];
    __syncthreads();

    // correction + gating: thread owns channel d, 16 tokens
    {
        int d = tid & 127, th = tid >> 7;
        int tk0 = th * 16;
        float Hreg[16];
        {
            const float4* Hp = (const float4*)&g_H[((size_t)bg*DI + d)*DS];
            #pragma unroll
            for (int q_ = 0; q_ < 4; ++q_) {
                float4 v = Hp[q_];
                Hreg[q_*4+0] = v.x; Hreg[q_*4+1] = v.y;
                Hreg[q_*4+2] = v.z; Hreg[q_*4+3] = v.w;
            }
        }
        float a0 = g_A[d*DS];
        bool chain = (g_chain[d] != 0);
        #pragma unroll 4
        for (int t_ = 0; t_ < 16; ++t_) {
            int tok = tk0 + t_;
            size_t gi = (size_t)(n0+tok)*DI + d;
            float cdv = g_cd[gi];
            float y   = g_pg[gi];
            float szv = g_z [gi];
            const float* Cr = Cs + tok*16;
            if (chain) {
                float q = __expf(a0 * cdv);
                float poly = Cr[15] * Hreg[15];
                #pragma unroll
                for (int s = 14; s >= 0; --s)
                    poly = fmaf(q, poly, Cr[s] * Hreg[s]);
                y += q * poly;
            } else {
                #pragma unroll
                for (int s = 0; s < DS; ++s)
                    y += Cr[s] * __expf(g_A[d*DS + s]*cdv) * Hreg[s];
            }
            ysT[d*YS_PITCH + tok] = y * szv;
        }
    }
    __syncthreads();

    // out_proj GEMM [64c x 32tok x 128K] from smem; 4c x 2tok microtile
    int cg = tid >> 4, tg = tid & 15;
    int c0 = cg*4, t0 = tg*2;
    float acc[4][2] = {};
    #pragma unroll 8
    for (int d = 0; d < DI; ++d) {
        float2 av = *(const float2*)&ysT[d*YS_PITCH + t0];
        float4 wv = *(const float4*)&wT[d*68 + c0];
        acc[0][0] += wv.x*av.x; acc[0][1] += wv.x*av.y;
        acc[1][0] += wv.y*av.x; acc[1][1] += wv.y*av.y;
        acc[2][0] += wv.z*av.x; acc[2][1] += wv.z*av.y;
        acc[3][0] += wv.w*av.x; acc[3][1] += wv.w*av.y;
    }
    float4 s0 = *(const float4*)&g_seq[(size_t)(n0 + t0 + 0)*CH + c0];
    float4 s1 = *(const float4*)&g_seq[(size_t)(n0 + t0 + 1)*CH + c0];
    const float* s0p = (const float*)&s0;
    const float* s1p = (const float*)&s1;
    #pragma unroll
    for (int i = 0; i < 4; ++i) {
        float2 ov;
        ov.x = acc[i][0] + s0p[i];
        ov.y = acc[i][1] + s1p[i];
        *(float2*)&out[((size_t)(b*CH + c0 + i))*LSEQ + l0 + t0] = ov;
    }
}

// ---------------- launch --------------------------------------------------
extern "C" void kernel_launch(void* const* d_in, const int* in_sizes, int n_in,
                              void* d_out, int out_size) {
    const float* x       = (const float*)d_in[0];
    const float* dwh_w   = (const float*)d_in[1];
    const float* dwh_b   = (const float*)d_in[2];
    const float* dww_w   = (const float*)d_in[3];
    const float* dww_b   = (const float*)d_in[4];
    const float* conv_w  = (const float*)d_in[5];
    const float* conv_b  = (const float*)d_in[6];
    const float* bn_g    = (const float*)d_in[7];
    const float* bn_b    = (const float*)d_in[8];
    const float* bn_m    = (const float*)d_in[9];
    const float* bn_v    = (const float*)d_in[10];
    const float* ln_g    = (const float*)d_in[11];
    const float* ln_b    = (const float*)d_in[12];
    const float* in_proj = (const float*)d_in[13];
    const float* convd_w = (const float*)d_in[14];
    const float* convd_b = (const float*)d_in[15];
    const float* x_proj  = (const float*)d_in[16];
    const float* dt_w    = (const float*)d_in[17];
    const float* dt_b    = (const float*)d_in[18];
    const float* A_log   = (const float*)d_in[19];
    const float* Dp      = (const float*)d_in[20];
    const float* out_w   = (const float*)d_in[21];
    float* out = (float*)d_out;

    cudaFuncSetAttribute(k_fuse1, cudaFuncAttributeMaxDynamicSharedMemorySize, 69120);
    cudaFuncSetAttribute(k_fuse2, cudaFuncAttributeMaxDynamicSharedMemorySize, 78640);
    cudaFuncSetAttribute(k_fuse4, cudaFuncAttributeMaxDynamicSharedMemorySize, 54272);

    k_fuse1<<<BZ*HH, 256, 69120>>>(x, dwh_w, dwh_b, dww_w, dww_b, conv_w, conv_b,
                                   bn_g, bn_b, bn_m, bn_v, ln_g, ln_b, in_proj, A_log, out_w);
    k_fuse2<<<BZ*GCH, 256, 78640>>>(convd_w, convd_b, x_proj, dt_w, dt_b, Dp);
    k_comb<<<64, 128>>>();
    k_fuse4<<<BZ*GCH*2, 256, 54272>>>(out);
}